// round 15
// baseline (speedup 1.0000x reference)
#include <cuda_runtime.h>
#include <cuda_bf16.h>
#include <cstdint>

#define Bn 8
#define Cc 256
#define CQn 32
#define Hh 128
#define Wn 128
#define HWn (Hh*Wn)

__device__ __nv_bfloat16 g_Wh[320*256], g_Wl[320*256];
__device__ float g_bs[320];
__device__ __nv_bfloat16 g_xh[(size_t)Bn*HWn*Cc], g_xl[(size_t)Bn*HWn*Cc]; // [b][p][c]
__device__ float g_q_hw[(size_t)Bn*HWn*CQn];        // [b][h][w][o]
__device__ float g_k_hw[(size_t)Bn*HWn*CQn];
__device__ __nv_bfloat16 g_va[(size_t)Bn*Cc*HWn];   // [b][c][h][w] bf16
__device__ __nv_bfloat16 g_vb[(size_t)Bn*Cc*HWn];   // [b][c][w][h] bf16
__device__ __nv_bfloat16 g_aH[(size_t)Bn*Wn*Hh*Hh]; // logits -> att (in place, bf16)
__device__ __nv_bfloat16 g_aW[(size_t)Bn*Hh*Wn*Wn];
__device__ __nv_bfloat16 g_oH[(size_t)Bn*HWn*Cc];   // [b][h][w][c] bf16

__device__ __forceinline__ float neg_inf_f() { return __int_as_float(0xff800000); }
__device__ __forceinline__ uint32_t splitf(float f) {
    __nv_bfloat16 h = __float2bfloat16(f);
    __nv_bfloat16 l = __float2bfloat16(f - __bfloat162float(h));
    return (uint32_t)__bfloat16_as_ushort(h) | ((uint32_t)__bfloat16_as_ushort(l) << 16);
}
__device__ __forceinline__ uint32_t pack2(float a, float b) {
    __nv_bfloat162 v = __floats2bfloat162_rn(a, b);
    return *reinterpret_cast<uint32_t*>(&v);
}
__device__ __forceinline__ float2 unpack2f(uint32_t u) {
    __nv_bfloat162 v = *reinterpret_cast<__nv_bfloat162*>(&u);
    return __bfloat1622float2(v);
}
__device__ __forceinline__ void unzip(uint2 p, uint32_t& hi, uint32_t& lo) {
    asm("prmt.b32 %0, %1, %2, 0x5410;" : "=r"(hi) : "r"(p.x), "r"(p.y));
    asm("prmt.b32 %0, %1, %2, 0x7632;" : "=r"(lo) : "r"(p.x), "r"(p.y));
}
__device__ __forceinline__ void mma16(float* d, uint32_t a0, uint32_t a1, uint32_t a2,
                                      uint32_t a3, uint32_t b0, uint32_t b1) {
    asm volatile("mma.sync.aligned.m16n8k16.row.col.f32.bf16.bf16.f32 "
                 "{%0,%1,%2,%3},{%4,%5,%6,%7},{%8,%9},{%0,%1,%2,%3};"
                 : "+f"(d[0]), "+f"(d[1]), "+f"(d[2]), "+f"(d[3])
                 : "r"(a0), "r"(a1), "r"(a2), "r"(a3), "r"(b0), "r"(b1));
}
__device__ __forceinline__ void ldm4(uint32_t* r, uint32_t addr) {
    asm volatile("ldmatrix.sync.aligned.m8n8.x4.shared.b16 {%0,%1,%2,%3}, [%4];"
                 : "=r"(r[0]), "=r"(r[1]), "=r"(r[2]), "=r"(r[3]) : "r"(addr));
}
__device__ __forceinline__ uint32_t s2u(const void* p) {
    return (uint32_t)__cvta_generic_to_shared(p);
}

// prep: split W rows [Wq;Wk;Wv]. grid 320, block 256.
__global__ __launch_bounds__(256) void prep_kernel(
    const float* __restrict__ Wq, const float* __restrict__ bq,
    const float* __restrict__ Wk, const float* __restrict__ bk,
    const float* __restrict__ Wv, const float* __restrict__ bv)
{
    const int r = blockIdx.x, t = threadIdx.x;
    const float* src; const float* bsrc; int o;
    if (r < 32)      { src = Wq; bsrc = bq; o = r; }
    else if (r < 64) { src = Wk; bsrc = bk; o = r - 32; }
    else             { src = Wv; bsrc = bv; o = r - 64; }
    float v = src[o*256 + t];
    __nv_bfloat16 h = __float2bfloat16(v);
    g_Wh[r*256 + t] = h;
    g_Wl[r*256 + t] = __float2bfloat16(v - __bfloat162float(h));
    if (t == 0) g_bs[r] = bsrc[o];
}

// xt: x[b][c][p] -> split bf16 [b][p][c]. grid (512,8,8), block 256.
__global__ __launch_bounds__(256) void xt_kernel(const float* __restrict__ x)
{
    __shared__ float tl[32][33];
    const int b = blockIdx.z, c0 = blockIdx.y*32, p0 = blockIdx.x*32;
    const int tx = threadIdx.x & 31, ty = threadIdx.x >> 5;
    #pragma unroll
    for (int i = 0; i < 4; i++) {
        int c = ty + i*8;
        tl[c][tx] = x[((size_t)(b*Cc + c0 + c))*HWn + p0 + tx];
    }
    __syncthreads();
    #pragma unroll
    for (int i = 0; i < 4; i++) {
        int p = ty + i*8;
        float v = tl[tx][p];
        __nv_bfloat16 h = __float2bfloat16(v);
        size_t idx = ((size_t)b*HWn + p0 + p)*Cc + c0 + tx;
        g_xh[idx] = h;
        g_xl[idx] = __float2bfloat16(v - __bfloat162float(h));
    }
}

// proj: per (mt,h,b): D[128 px x 64 oc].
// mt==0 (q,k): 2-pass (xh*Wh + xl*Wh). mt>=1 (v): 1-pass.
// Double-buffered smem, ONE sync per k-chunk. grid (5,128,8), block 256.
// Dyn smem: 2 buffers x 6400 words (AHI@0, ALO@2560, BHI@5120).
#define PROJ_DYN (2*6400*4)
__global__ __launch_bounds__(256) void proj_mma()
{
    extern __shared__ __align__(16) uint32_t pool[];
    __shared__ float s_bias[64];
    const int t = threadIdx.x, wid = t >> 5, lane = t & 31;
    const int g8 = lane >> 2, tig = lane & 3;
    const int warp_m = wid & 3, warp_n = wid >> 2;
    const int mt = blockIdx.x, h = blockIdx.y, b = blockIdx.z;
    const int px0 = h * 128;
    const bool hiPrec = (mt == 0);
    if (t < 64) s_bias[t] = g_bs[mt*64 + t];

    const __nv_bfloat16* Xh = g_xh + ((size_t)b*HWn + px0)*Cc;
    const __nv_bfloat16* Xl = g_xl + ((size_t)b*HWn + px0)*Cc;
    const __nv_bfloat16* Wh = g_Wh + (size_t)mt*64*Cc;

    const uint32_t pbase = s2u(pool);
    const uint32_t aRow = (uint32_t)(lane & 15);
    const uint32_t aCol = (uint32_t)((lane >> 4) * 16);
    const uint32_t bRow = (uint32_t)((lane & 7) + ((lane >> 4) << 3));
    const uint32_t bCol = (uint32_t)(((lane >> 3) & 1) * 16);

    float acc[2][4][4] = {};
    const int ar = t >> 1, aw = (t & 1)*8;
    const int br = t >> 2, bw = (t & 3)*4;

    uint4 ah0, ah1, bh, al0, al1;
    {   // preload chunk 0
        const size_t ae = (size_t)ar*Cc + aw*2;
        const size_t be = (size_t)br*Cc + bw*2;
        ah0 = *(const uint4*)(Xh + ae); ah1 = *(const uint4*)(Xh + ae + 8);
        bh  = *(const uint4*)(Wh + be);
        if (hiPrec) { al0 = *(const uint4*)(Xl + ae); al1 = *(const uint4*)(Xl + ae + 8); }
    }

    for (int kc = 0; kc < 8; kc++) {
        const uint32_t bufw = (kc & 1) * 6400;
        *(uint4*)&pool[bufw + ar*20 + aw]       = ah0;
        *(uint4*)&pool[bufw + ar*20 + aw + 4]   = ah1;
        *(uint4*)&pool[bufw + 5120 + br*20 + bw]= bh;
        if (hiPrec) {
            *(uint4*)&pool[bufw + 2560 + ar*20 + aw]     = al0;
            *(uint4*)&pool[bufw + 2560 + ar*20 + aw + 4] = al1;
        }
        if (kc < 7) {   // prefetch next chunk into regs
            const size_t ae = (size_t)ar*Cc + (kc+1)*32 + aw*2;
            const size_t be = (size_t)br*Cc + (kc+1)*32 + bw*2;
            ah0 = *(const uint4*)(Xh + ae); ah1 = *(const uint4*)(Xh + ae + 8);
            bh  = *(const uint4*)(Wh + be);
            if (hiPrec) { al0 = *(const uint4*)(Xl + ae); al1 = *(const uint4*)(Xl + ae + 8); }
        }
        __syncthreads();
        const uint32_t bufb = pbase + (kc & 1) * 25600;
        #pragma unroll
        for (int ks = 0; ks < 2; ks++) {
            const uint32_t ksb = ks*32;
            uint32_t ahf[2][4], alf[2][4], bf[2][4];
            #pragma unroll
            for (int mi = 0; mi < 2; mi++) {
                const uint32_t rowm = (warp_m*32 + mi*16 + aRow)*80 + ksb + aCol;
                ldm4(ahf[mi], bufb + rowm);
                if (hiPrec) ldm4(alf[mi], bufb + 10240 + rowm);
            }
            #pragma unroll
            for (int pi = 0; pi < 2; pi++) {
                const uint32_t rown = (warp_n*32 + pi*16 + bRow)*80 + ksb + bCol;
                ldm4(bf[pi], bufb + 20480 + rown);
            }
            #pragma unroll
            for (int pi = 0; pi < 2; pi++)
                #pragma unroll
                for (int half = 0; half < 2; half++) {
                    const int ni = pi*2 + half;
                    const uint32_t b0 = bf[pi][half*2], b1 = bf[pi][half*2 + 1];
                    #pragma unroll
                    for (int mi = 0; mi < 2; mi++) {
                        mma16(acc[mi][ni], ahf[mi][0], ahf[mi][1], ahf[mi][2], ahf[mi][3], b0, b1);
                        if (hiPrec)
                            mma16(acc[mi][ni], alf[mi][0], alf[mi][1], alf[mi][2], alf[mi][3], b0, b1);
                    }
                }
        }
    }

    if (mt == 0) {
        #pragma unroll
        for (int mi = 0; mi < 2; mi++)
            #pragma unroll
            for (int ni = 0; ni < 4; ni++) {
                const int n = warp_n*32 + ni*8 + tig*2;
                const float b0 = s_bias[n], b1 = s_bias[n+1];
                float* hwp = (n < 32 ? g_q_hw : g_k_hw);
                const int o = n & 31;
                #pragma unroll
                for (int hf = 0; hf < 2; hf++) {
                    const int w = warp_m*32 + mi*16 + g8 + hf*8;
                    float2 v = {acc[mi][ni][hf*2] + b0, acc[mi][ni][hf*2+1] + b1};
                    *(float2*)(hwp + ((size_t)(b*Hh + h)*Wn + w)*CQn + o) = v;
                }
            }
    } else {
        float* tb = (float*)pool;   // [64 c][132 px]
        __syncthreads();
        #pragma unroll
        for (int mi = 0; mi < 2; mi++)
            #pragma unroll
            for (int ni = 0; ni < 4; ni++) {
                const int n = warp_n*32 + ni*8 + tig*2;
                const float b0 = s_bias[n], b1 = s_bias[n+1];
                #pragma unroll
                for (int hf = 0; hf < 2; hf++) {
                    const int w = warp_m*32 + mi*16 + g8 + hf*8;
                    tb[n*132 + w]     = acc[mi][ni][hf*2]   + b0;
                    tb[(n+1)*132 + w] = acc[mi][ni][hf*2+1] + b1;
                }
            }
        __syncthreads();
        const int c = t >> 2, p4 = (t & 3)*32;
        uint32_t* dst = (uint32_t*)(g_va + ((size_t)(b*Cc + (mt-1)*64 + c))*HWn + px0 + p4);
        #pragma unroll
        for (int i = 0; i < 32; i += 8) {
            uint4 u;
            u.x = pack2(tb[c*132+p4+i  ], tb[c*132+p4+i+1]);
            u.y = pack2(tb[c*132+p4+i+2], tb[c*132+p4+i+3]);
            u.z = pack2(tb[c*132+p4+i+4], tb[c*132+p4+i+5]);
            u.w = pack2(tb[c*132+p4+i+6], tb[c*132+p4+i+7]);
            *(uint4*)(dst + i/2) = u;
        }
    }
}

// vb: bf16 transpose g_va[c][h][w] -> g_vb[c][w][h]. grid (2,2,Bn*Cc), block 256.
__global__ __launch_bounds__(256) void vb_kernel()
{
    __shared__ uint32_t sm[64][33];
    const int bc = blockIdx.z, w0 = blockIdx.x*64, h0 = blockIdx.y*64;
    const int t = threadIdx.x;
    const uint32_t* src = (const uint32_t*)g_va + (size_t)bc*(HWn/2);
    uint32_t* dst = (uint32_t*)g_vb + (size_t)bc*(HWn/2);
    #pragma unroll
    for (int i = 0; i < 8; i++) {
        const int idx = i*256 + t, r = idx >> 5, wd = idx & 31;
        sm[r][wd] = src[(size_t)(h0 + r)*64 + w0/2 + wd];
    }
    __syncthreads();
    #pragma unroll
    for (int i = 0; i < 4; i++) {
        const int idx = i*256 + t, wp = idx >> 5, hp = idx & 31;
        uint32_t u1 = sm[2*hp][wp], u2 = sm[2*hp+1][wp];
        uint32_t lo, hi;
        asm("prmt.b32 %0, %1, %2, 0x5410;" : "=r"(lo) : "r"(u1), "r"(u2));
        asm("prmt.b32 %0, %1, %2, 0x7632;" : "=r"(hi) : "r"(u1), "r"(u2));
        dst[(size_t)(w0 + 2*wp  )*64 + h0/2 + hp] = lo;
        dst[(size_t)(w0 + 2*wp+1)*64 + h0/2 + hp] = hi;
    }
}

// score: logits = Q@K^T (K=32), bf16 2-pass. grid (1024, 2): y=0 -> ISH.
// Writes bf16 logits. block 256.
__global__ __launch_bounds__(256) void score_mma()
{
    __shared__ __align__(16) uint32_t Qs[128][36], Ks[128][36];
    const int bs = blockIdx.x, t = threadIdx.x;
    const bool ISH = (blockIdx.y == 0);
    const int wid = t >> 5, lane = t & 31, g8 = lane >> 2, tig = lane & 3;
    const int warp_m = wid & 3, warp_n = wid >> 2;
    const int b = bs >> 7, sfix = bs & 127;
    const size_t base = (size_t)b*HWn*CQn +
        (ISH ? (size_t)sfix*CQn : (size_t)sfix*Wn*CQn);
    const size_t rstride = ISH ? (size_t)Wn*CQn : (size_t)CQn;
    const float* Q = g_q_hw + base;
    const float* K = g_k_hw + base;
    uint32_t* O = (uint32_t*)(ISH ? g_aH : g_aW) + (size_t)bs*128*64;

    #pragma unroll
    for (int i = 0; i < 4; i++) {
        const int idx = i*256 + t, r = idx >> 3, kq = (idx & 7)*4;
        float4 qv = *(const float4*)(Q + (size_t)r*rstride + kq);
        float4 kv = *(const float4*)(K + (size_t)r*rstride + kq);
        uint4 qp = {splitf(qv.x), splitf(qv.y), splitf(qv.z), splitf(qv.w)};
        uint4 kp = {splitf(kv.x), splitf(kv.y), splitf(kv.z), splitf(kv.w)};
        *(uint4*)&Qs[r][kq] = qp;
        *(uint4*)&Ks[r][kq] = kp;
    }
    __syncthreads();

    float acc[2][8][4] = {};
    #pragma unroll
    for (int ks = 0; ks < 2; ks++) {
        const int k0 = ks*16;
        uint32_t ah[2][4], al[2][4];
        #pragma unroll
        for (int mi = 0; mi < 2; mi++) {
            const int m = warp_m*32 + mi*16;
            unzip(*(uint2*)&Qs[m+g8  ][k0 + 2*tig],     ah[mi][0], al[mi][0]);
            unzip(*(uint2*)&Qs[m+g8+8][k0 + 2*tig],     ah[mi][1], al[mi][1]);
            unzip(*(uint2*)&Qs[m+g8  ][k0 + 8 + 2*tig], ah[mi][2], al[mi][2]);
            unzip(*(uint2*)&Qs[m+g8+8][k0 + 8 + 2*tig], ah[mi][3], al[mi][3]);
        }
        #pragma unroll
        for (int ni = 0; ni < 8; ni++) {
            const int n = warp_n*64 + ni*8 + g8;
            uint32_t bh0, bl0, bh1, bl1;
            unzip(*(uint2*)&Ks[n][k0 + 2*tig],     bh0, bl0);
            unzip(*(uint2*)&Ks[n][k0 + 8 + 2*tig], bh1, bl1);
            #pragma unroll
            for (int mi = 0; mi < 2; mi++) {
                mma16(acc[mi][ni], ah[mi][0], ah[mi][1], ah[mi][2], ah[mi][3], bh0, bh1);
                mma16(acc[mi][ni], al[mi][0], al[mi][1], al[mi][2], al[mi][3], bh0, bh1);
            }
        }
    }
    #pragma unroll
    for (int mi = 0; mi < 2; mi++)
        #pragma unroll
        for (int ni = 0; ni < 8; ni++) {
            const int n = warp_n*64 + ni*8 + tig*2;
            #pragma unroll
            for (int hf = 0; hf < 2; hf++) {
                const int m = warp_m*32 + mi*16 + g8 + hf*8;
                float d0 = acc[mi][ni][hf*2], d1 = acc[mi][ni][hf*2+1];
                if (ISH) { if (n == m) d0 = neg_inf_f(); if (n+1 == m) d1 = neg_inf_f(); }
                O[(size_t)m*64 + n/2] = pack2(d0, d1);
            }
        }
}

// softmax: reads bf16 logits, writes bf16 att in place. grid 16384, block 256.
__global__ __launch_bounds__(256) void softmax_kernel()
{
    const int wid = blockIdx.x*8 + (threadIdx.x >> 5), lane = threadIdx.x & 31;
    const int b = wid >> 14, hw = wid & 16383, h = hw >> 7, w = hw & 127;
    const size_t rH = (size_t)(b*Wn + w)*Hh + h;
    const size_t rW = (size_t)(b*Hh + h)*Wn + w;
    uint32_t* aH = (uint32_t*)g_aH + rH*64;
    uint32_t* aW = (uint32_t*)g_aW + rW*64;
    uint2 uh = *(uint2*)(aH + lane*2);
    uint2 uw = *(uint2*)(aW + lane*2);
    float2 h01 = unpack2f(uh.x), h23 = unpack2f(uh.y);
    float2 w01 = unpack2f(uw.x), w23 = unpack2f(uw.y);
    float m = fmaxf(fmaxf(fmaxf(h01.x,h01.y),fmaxf(h23.x,h23.y)),
                    fmaxf(fmaxf(w01.x,w01.y),fmaxf(w23.x,w23.y)));
    #pragma unroll
    for (int off = 16; off; off >>= 1) m = fmaxf(m, __shfl_xor_sync(~0u, m, off));
    h01.x=__expf(h01.x-m); h01.y=__expf(h01.y-m); h23.x=__expf(h23.x-m); h23.y=__expf(h23.y-m);
    w01.x=__expf(w01.x-m); w01.y=__expf(w01.y-m); w23.x=__expf(w23.x-m); w23.y=__expf(w23.y-m);
    float s = h01.x+h01.y+h23.x+h23.y+w01.x+w01.y+w23.x+w23.y;
    #pragma unroll
    for (int off = 16; off; off >>= 1) s += __shfl_xor_sync(~0u, s, off);
    const float inv = 1.f/s;
    *(uint2*)(aH + lane*2) = make_uint2(pack2(h01.x*inv, h01.y*inv), pack2(h23.x*inv, h23.y*inv));
    *(uint2*)(aW + lane*2) = make_uint2(pack2(w01.x*inv, w01.y*inv), pack2(w23.x*inv, w23.y*inv));
}

// out<ISH>: D[128 spatial x 128 c] = att(bf16) @ v^T(bf16), ldmatrix feed,
// double-buffered (ONE sync per chunk). ISH: writes g_oH[b][h][w][c].
// !ISH: adds oH, emits gamma*(D+oH)+x -> out. grid (2,1024), block 256.
template <bool ISH>
__global__ __launch_bounds__(256) void out_mma(const float* __restrict__ x,
                                               const float* __restrict__ gamma,
                                               float* __restrict__ out)
{
    __shared__ __align__(16) uint32_t sm[10240];   // 2 bufs x (As 2560 | Bs 2560); tb reuse
    const int t = threadIdx.x, wid = t >> 5, lane = t & 31;
    const int g8 = lane >> 2, tig = lane & 3;
    const int warp_m = wid & 3, warp_n = wid >> 2;
    const int bs = blockIdx.y, b = bs >> 7, s = bs & 127;
    const int c0 = blockIdx.x * 128;
    const uint32_t* A = (const uint32_t*)(ISH ? g_aH : g_aW) + (size_t)bs*128*64;
    const uint32_t* V = (const uint32_t*)(ISH ? g_vb : g_va) + (size_t)b*Cc*(HWn/2) + s*64;

    const uint32_t sbase = s2u(sm);
    const uint32_t aRow = (uint32_t)(lane & 15);
    const uint32_t aCol = (uint32_t)((lane >> 4) * 16);
    const uint32_t bRow = (uint32_t)((lane & 7) + ((lane >> 4) << 3));
    const uint32_t bCol = (uint32_t)(((lane >> 3) & 1) * 16);

    float acc[2][8][4] = {};
    const int r2 = t >> 1, wq = (t & 1)*8;
    uint4 a0, a1, b0, b1;
    a0 = *(const uint4*)(A + (size_t)r2*64 + wq);
    a1 = *(const uint4*)(A + (size_t)r2*64 + wq + 4);
    b0 = *(const uint4*)(V + (size_t)(c0 + r2)*(HWn/2) + wq);
    b1 = *(const uint4*)(V + (size_t)(c0 + r2)*(HWn/2) + wq + 4);

    for (int kc = 0; kc < 4; kc++) {
        const uint32_t bufw = (kc & 1) * 5120;
        *(uint4*)&sm[bufw + r2*20 + wq]          = a0;
        *(uint4*)&sm[bufw + r2*20 + wq + 4]      = a1;
        *(uint4*)&sm[bufw + 2560 + r2*20 + wq]   = b0;
        *(uint4*)&sm[bufw + 2560 + r2*20 + wq+4] = b1;
        if (kc < 3) {
            a0 = *(const uint4*)(A + (size_t)r2*64 + (kc+1)*16 + wq);
            a1 = *(const uint4*)(A + (size_t)r2*64 + (kc+1)*16 + wq + 4);
            b0 = *(const uint4*)(V + (size_t)(c0 + r2)*(HWn/2) + (kc+1)*16 + wq);
            b1 = *(const uint4*)(V + (size_t)(c0 + r2)*(HWn/2) + (kc+1)*16 + wq + 4);
        }
        __syncthreads();
        const uint32_t bufb = sbase + (kc & 1) * 20480;
        #pragma unroll
        for (int ks = 0; ks < 2; ks++) {
            const uint32_t ksb = ks*32;
            uint32_t af[2][4], bf[4][4];
            #pragma unroll
            for (int mi = 0; mi < 2; mi++)
                ldm4(af[mi], bufb + (warp_m*32 + mi*16 + aRow)*80 + ksb + aCol);
            #pragma unroll
            for (int pi = 0; pi < 4; pi++)
                ldm4(bf[pi], bufb + 10240 + (warp_n*64 + pi*16 + bRow)*80 + ksb + bCol);
            #pragma unroll
            for (int pi = 0; pi < 4; pi++)
                #pragma unroll
                for (int half = 0; half < 2; half++) {
                    const int ni = pi*2 + half;
                    const uint32_t bb0 = bf[pi][half*2], bb1 = bf[pi][half*2 + 1];
                    #pragma unroll
                    for (int mi = 0; mi < 2; mi++)
                        mma16(acc[mi][ni], af[mi][0], af[mi][1], af[mi][2], af[mi][3], bb0, bb1);
                }
        }
    }

    if (ISH) {
        uint32_t* Ob = (uint32_t*)g_oH;
        #pragma unroll
        for (int mi = 0; mi < 2; mi++)
            #pragma unroll
            for (int ni = 0; ni < 8; ni++) {
                const int m = warp_m*32 + mi*16 + g8;
                const int n = c0 + warp_n*64 + ni*8 + tig*2;
                Ob[((size_t)(b*Hh + m)*Wn + s)*128 + n/2]   = pack2(acc[mi][ni][0], acc[mi][ni][1]);
                Ob[((size_t)(b*Hh + m+8)*Wn + s)*128 + n/2] = pack2(acc[mi][ni][2], acc[mi][ni][3]);
            }
    } else {
        const float gm = gamma[0];
        const uint32_t* o1 = (const uint32_t*)g_oH + (size_t)(b*Hh + s)*Wn*128;
        #pragma unroll
        for (int mi = 0; mi < 2; mi++)
            #pragma unroll
            for (int ni = 0; ni < 8; ni++) {
                const int m = warp_m*32 + mi*16 + g8;
                const int n = c0 + warp_n*64 + ni*8 + tig*2;
                float2 p0 = unpack2f(o1[(size_t)m*128 + n/2]);
                float2 p1 = unpack2f(o1[(size_t)(m+8)*128 + n/2]);
                acc[mi][ni][0] += p0.x; acc[mi][ni][1] += p0.y;
                acc[mi][ni][2] += p1.x; acc[mi][ni][3] += p1.y;
            }
        float* tb = (float*)sm;     // [32][132] floats
        #pragma unroll
        for (int cc = 0; cc < 4; cc++) {
            __syncthreads();
            if (warp_n == (cc >> 1)) {
                const int nib = (cc & 1)*4;
                #pragma unroll
                for (int mi = 0; mi < 2; mi++)
                    #pragma unroll
                    for (int nj = 0; nj < 4; nj++) {
                        const int ni = nib + nj;
                        const int nl = nj*8 + tig*2;
                        const int m = warp_m*32 + mi*16 + g8;
                        tb[nl*132 + m]       = acc[mi][ni][0];
                        tb[(nl+1)*132 + m]   = acc[mi][ni][1];
                        tb[nl*132 + m+8]     = acc[mi][ni][2];
                        tb[(nl+1)*132 + m+8] = acc[mi][ni][3];
                    }
            }
            __syncthreads();
            #pragma unroll
            for (int p = 0; p < 4; p++) {
                const int ci = (t >> 5) + p*8;
                const int w4 = (t & 31)*4;
                const size_t oidx = ((size_t)(b*Cc + c0 + cc*32 + ci)*Hh + s)*Wn + w4;
                float4 xr = *(const float4*)(x + oidx);
                float4 r;
                r.x = gm*tb[ci*132 + w4  ] + xr.x;
                r.y = gm*tb[ci*132 + w4+1] + xr.y;
                r.z = gm*tb[ci*132 + w4+2] + xr.z;
                r.w = gm*tb[ci*132 + w4+3] + xr.w;
                *(float4*)(out + oidx) = r;
            }
        }
    }
}

extern "C" void kernel_launch(void* const* d_in, const int* in_sizes, int n_in,
                              void* d_out, int out_size)
{
    const float* x     = (const float*)d_in[0];
    const float* Wq    = (const float*)d_in[1];
    const float* bq    = (const float*)d_in[2];
    const float* Wk    = (const float*)d_in[3];
    const float* bk    = (const float*)d_in[4];
    const float* Wv    = (const float*)d_in[5];
    const float* bv    = (const float*)d_in[6];
    const float* gamma = (const float*)d_in[7];
    float* out = (float*)d_out;

    static bool attr_set = false;
    if (!attr_set) {
        cudaFuncSetAttribute(proj_mma, cudaFuncAttributeMaxDynamicSharedMemorySize, PROJ_DYN);
        attr_set = true;
    }

    prep_kernel<<<320, 256>>>(Wq, bq, Wk, bk, Wv, bv);
    xt_kernel<<<dim3(512, 8, 8), 256>>>(x);
    proj_mma<<<dim3(5, 128, 8), 256, PROJ_DYN>>>();
    vb_kernel<<<dim3(2, 2, Bn*Cc), 256>>>();
    score_mma<<<dim3(1024, 2), 256>>>();
    softmax_kernel<<<16384, 256>>>();
    out_mma<true ><<<dim3(2, 1024), 256>>>(x, gamma, out);
    out_mma<false><<<dim3(2, 1024), 256>>>(x, gamma, out);
}

// round 16
// speedup vs baseline: 1.0638x; 1.0638x over previous
#include <cuda_runtime.h>
#include <cuda_bf16.h>
#include <cstdint>

#define Bn 8
#define Cc 256
#define CQn 32
#define Hh 128
#define Wn 128
#define HWn (Hh*Wn)

__device__ __nv_bfloat16 g_Wh[320*256], g_Wl[320*256];
__device__ float g_bs[320];
__device__ __nv_bfloat16 g_xh[(size_t)Bn*HWn*Cc], g_xl[(size_t)Bn*HWn*Cc]; // [b][p][c]
__device__ float g_q_hw[(size_t)Bn*HWn*CQn];        // [b][h][w][o]
__device__ float g_k_hw[(size_t)Bn*HWn*CQn];
__device__ __nv_bfloat16 g_va[(size_t)Bn*Cc*HWn];   // [b][c][h][w] bf16
__device__ __nv_bfloat16 g_vb[(size_t)Bn*Cc*HWn];   // [b][c][w][h] bf16
__device__ __nv_bfloat16 g_aH[(size_t)Bn*Wn*Hh*Hh]; // logits -> att (in place, bf16)
__device__ __nv_bfloat16 g_aW[(size_t)Bn*Hh*Wn*Wn];
__device__ __nv_bfloat16 g_oH[(size_t)Bn*HWn*Cc];   // [b][h][w][c] bf16

__device__ __forceinline__ float neg_inf_f() { return __int_as_float(0xff800000); }
__device__ __forceinline__ uint32_t splitf(float f) {
    __nv_bfloat16 h = __float2bfloat16(f);
    __nv_bfloat16 l = __float2bfloat16(f - __bfloat162float(h));
    return (uint32_t)__bfloat16_as_ushort(h) | ((uint32_t)__bfloat16_as_ushort(l) << 16);
}
__device__ __forceinline__ uint32_t pack2(float a, float b) {
    __nv_bfloat162 v = __floats2bfloat162_rn(a, b);
    return *reinterpret_cast<uint32_t*>(&v);
}
__device__ __forceinline__ float2 unpack2f(uint32_t u) {
    __nv_bfloat162 v = *reinterpret_cast<__nv_bfloat162*>(&u);
    return __bfloat1622float2(v);
}
__device__ __forceinline__ void unzip(uint2 p, uint32_t& hi, uint32_t& lo) {
    asm("prmt.b32 %0, %1, %2, 0x5410;" : "=r"(hi) : "r"(p.x), "r"(p.y));
    asm("prmt.b32 %0, %1, %2, 0x7632;" : "=r"(lo) : "r"(p.x), "r"(p.y));
}
__device__ __forceinline__ void mma16(float* d, uint32_t a0, uint32_t a1, uint32_t a2,
                                      uint32_t a3, uint32_t b0, uint32_t b1) {
    asm volatile("mma.sync.aligned.m16n8k16.row.col.f32.bf16.bf16.f32 "
                 "{%0,%1,%2,%3},{%4,%5,%6,%7},{%8,%9},{%0,%1,%2,%3};"
                 : "+f"(d[0]), "+f"(d[1]), "+f"(d[2]), "+f"(d[3])
                 : "r"(a0), "r"(a1), "r"(a2), "r"(a3), "r"(b0), "r"(b1));
}
__device__ __forceinline__ void ldm4(uint32_t* r, uint32_t addr) {
    asm volatile("ldmatrix.sync.aligned.m8n8.x4.shared.b16 {%0,%1,%2,%3}, [%4];"
                 : "=r"(r[0]), "=r"(r[1]), "=r"(r[2]), "=r"(r[3]) : "r"(addr));
}
__device__ __forceinline__ uint32_t s2u(const void* p) {
    return (uint32_t)__cvta_generic_to_shared(p);
}

// prep: split W rows [Wq;Wk;Wv]. grid 320, block 256.
__global__ __launch_bounds__(256) void prep_kernel(
    const float* __restrict__ Wq, const float* __restrict__ bq,
    const float* __restrict__ Wk, const float* __restrict__ bk,
    const float* __restrict__ Wv, const float* __restrict__ bv)
{
    const int r = blockIdx.x, t = threadIdx.x;
    const float* src; const float* bsrc; int o;
    if (r < 32)      { src = Wq; bsrc = bq; o = r; }
    else if (r < 64) { src = Wk; bsrc = bk; o = r - 32; }
    else             { src = Wv; bsrc = bv; o = r - 64; }
    float v = src[o*256 + t];
    __nv_bfloat16 h = __float2bfloat16(v);
    g_Wh[r*256 + t] = h;
    g_Wl[r*256 + t] = __float2bfloat16(v - __bfloat162float(h));
    if (t == 0) g_bs[r] = bsrc[o];
}

// xt: x[b][c][p] -> split bf16 [b][p][c]. grid (512,8,8), block 256.
__global__ __launch_bounds__(256) void xt_kernel(const float* __restrict__ x)
{
    __shared__ float tl[32][33];
    const int b = blockIdx.z, c0 = blockIdx.y*32, p0 = blockIdx.x*32;
    const int tx = threadIdx.x & 31, ty = threadIdx.x >> 5;
    #pragma unroll
    for (int i = 0; i < 4; i++) {
        int c = ty + i*8;
        tl[c][tx] = x[((size_t)(b*Cc + c0 + c))*HWn + p0 + tx];
    }
    __syncthreads();
    #pragma unroll
    for (int i = 0; i < 4; i++) {
        int p = ty + i*8;
        float v = tl[tx][p];
        __nv_bfloat16 h = __float2bfloat16(v);
        size_t idx = ((size_t)b*HWn + p0 + p)*Cc + c0 + tx;
        g_xh[idx] = h;
        g_xl[idx] = __float2bfloat16(v - __bfloat162float(h));
    }
}

// proj: per (mt,h,b): D[128 px x 64 oc].
// mt==0 (q,k): 2-pass (xh*Wh + xl*Wh). mt>=1 (v): 1-pass.
// Fragment feeding via ldmatrix.x4, single-buffer. grid (5,128,8), block 256.
__global__ __launch_bounds__(256) void proj_mma()
{
    __shared__ __align__(16) uint32_t pool[8448];  // AHI@0 ALO@2560 BHI@5120 (stride 20w); tb reuse
    __shared__ float s_bias[64];
    const int t = threadIdx.x, wid = t >> 5, lane = t & 31;
    const int g8 = lane >> 2, tig = lane & 3;
    const int warp_m = wid & 3, warp_n = wid >> 2;
    const int mt = blockIdx.x, h = blockIdx.y, b = blockIdx.z;
    const int px0 = h * 128;
    const bool hiPrec = (mt == 0);
    if (t < 64) s_bias[t] = g_bs[mt*64 + t];

    const __nv_bfloat16* Xh = g_xh + ((size_t)b*HWn + px0)*Cc;
    const __nv_bfloat16* Xl = g_xl + ((size_t)b*HWn + px0)*Cc;
    const __nv_bfloat16* Wh = g_Wh + (size_t)mt*64*Cc;

    const uint32_t pbase = s2u(pool);
    const uint32_t aRow = (uint32_t)(lane & 15);
    const uint32_t aCol = (uint32_t)((lane >> 4) * 16);
    const uint32_t bRow = (uint32_t)((lane & 7) + ((lane >> 4) << 3));
    const uint32_t bCol = (uint32_t)(((lane >> 3) & 1) * 16);

    float acc[2][4][4] = {};
    const int ar = t >> 1, aw = (t & 1)*8;
    const int br = t >> 2, bw = (t & 3)*4;

    for (int kc = 0; kc < 8; kc++) {
        const size_t ae = (size_t)ar*Cc + kc*32 + aw*2;
        const size_t be = (size_t)br*Cc + kc*32 + bw*2;
        uint4 ah0 = *(const uint4*)(Xh + ae), ah1 = *(const uint4*)(Xh + ae + 8);
        uint4 bh  = *(const uint4*)(Wh + be);
        uint4 al0, al1;
        if (hiPrec) {
            al0 = *(const uint4*)(Xl + ae); al1 = *(const uint4*)(Xl + ae + 8);
        }
        __syncthreads();
        *(uint4*)&pool[ar*20 + aw]        = ah0;
        *(uint4*)&pool[ar*20 + aw + 4]    = ah1;
        *(uint4*)&pool[5120 + br*20 + bw] = bh;
        if (hiPrec) {
            *(uint4*)&pool[2560 + ar*20 + aw]   = al0;
            *(uint4*)&pool[2560 + ar*20 + aw+4] = al1;
        }
        __syncthreads();
        #pragma unroll
        for (int ks = 0; ks < 2; ks++) {
            const uint32_t ksb = ks*32;
            uint32_t ahf[2][4], alf[2][4], bf[2][4];
            #pragma unroll
            for (int mi = 0; mi < 2; mi++) {
                const uint32_t rowm = (warp_m*32 + mi*16 + aRow)*80 + ksb + aCol;
                ldm4(ahf[mi], pbase + rowm);
                if (hiPrec) ldm4(alf[mi], pbase + 10240 + rowm);
            }
            #pragma unroll
            for (int pi = 0; pi < 2; pi++) {
                const uint32_t rown = (warp_n*32 + pi*16 + bRow)*80 + ksb + bCol;
                ldm4(bf[pi], pbase + 20480 + rown);
            }
            #pragma unroll
            for (int pi = 0; pi < 2; pi++)
                #pragma unroll
                for (int half = 0; half < 2; half++) {
                    const int ni = pi*2 + half;
                    const uint32_t b0 = bf[pi][half*2], b1 = bf[pi][half*2 + 1];
                    #pragma unroll
                    for (int mi = 0; mi < 2; mi++) {
                        mma16(acc[mi][ni], ahf[mi][0], ahf[mi][1], ahf[mi][2], ahf[mi][3], b0, b1);
                        if (hiPrec)
                            mma16(acc[mi][ni], alf[mi][0], alf[mi][1], alf[mi][2], alf[mi][3], b0, b1);
                    }
                }
        }
    }

    if (mt == 0) {
        #pragma unroll
        for (int mi = 0; mi < 2; mi++)
            #pragma unroll
            for (int ni = 0; ni < 4; ni++) {
                const int n = warp_n*32 + ni*8 + tig*2;
                const float b0 = s_bias[n], b1 = s_bias[n+1];
                float* hwp = (n < 32 ? g_q_hw : g_k_hw);
                const int o = n & 31;
                #pragma unroll
                for (int hf = 0; hf < 2; hf++) {
                    const int w = warp_m*32 + mi*16 + g8 + hf*8;
                    float2 v = {acc[mi][ni][hf*2] + b0, acc[mi][ni][hf*2+1] + b1};
                    *(float2*)(hwp + ((size_t)(b*Hh + h)*Wn + w)*CQn + o) = v;
                }
            }
    } else {
        float* tb = (float*)pool;   // [64 c][132 px]
        __syncthreads();
        #pragma unroll
        for (int mi = 0; mi < 2; mi++)
            #pragma unroll
            for (int ni = 0; ni < 4; ni++) {
                const int n = warp_n*32 + ni*8 + tig*2;
                const float b0 = s_bias[n], b1 = s_bias[n+1];
                #pragma unroll
                for (int hf = 0; hf < 2; hf++) {
                    const int w = warp_m*32 + mi*16 + g8 + hf*8;
                    tb[n*132 + w]     = acc[mi][ni][hf*2]   + b0;
                    tb[(n+1)*132 + w] = acc[mi][ni][hf*2+1] + b1;
                }
            }
        __syncthreads();
        const int c = t >> 2, p4 = (t & 3)*32;
        uint32_t* dst = (uint32_t*)(g_va + ((size_t)(b*Cc + (mt-1)*64 + c))*HWn + px0 + p4);
        #pragma unroll
        for (int i = 0; i < 32; i += 8) {
            uint4 u;
            u.x = pack2(tb[c*132+p4+i  ], tb[c*132+p4+i+1]);
            u.y = pack2(tb[c*132+p4+i+2], tb[c*132+p4+i+3]);
            u.z = pack2(tb[c*132+p4+i+4], tb[c*132+p4+i+5]);
            u.w = pack2(tb[c*132+p4+i+6], tb[c*132+p4+i+7]);
            *(uint4*)(dst + i/2) = u;
        }
    }
}

// vb: bf16 transpose g_va[c][h][w] -> g_vb[c][w][h]. grid (2,2,Bn*Cc), block 256.
__global__ __launch_bounds__(256) void vb_kernel()
{
    __shared__ uint32_t sm[64][33];
    const int bc = blockIdx.z, w0 = blockIdx.x*64, h0 = blockIdx.y*64;
    const int t = threadIdx.x;
    const uint32_t* src = (const uint32_t*)g_va + (size_t)bc*(HWn/2);
    uint32_t* dst = (uint32_t*)g_vb + (size_t)bc*(HWn/2);
    #pragma unroll
    for (int i = 0; i < 8; i++) {
        const int idx = i*256 + t, r = idx >> 5, wd = idx & 31;
        sm[r][wd] = src[(size_t)(h0 + r)*64 + w0/2 + wd];
    }
    __syncthreads();
    #pragma unroll
    for (int i = 0; i < 4; i++) {
        const int idx = i*256 + t, wp = idx >> 5, hp = idx & 31;
        uint32_t u1 = sm[2*hp][wp], u2 = sm[2*hp+1][wp];
        uint32_t lo, hi;
        asm("prmt.b32 %0, %1, %2, 0x5410;" : "=r"(lo) : "r"(u1), "r"(u2));
        asm("prmt.b32 %0, %1, %2, 0x7632;" : "=r"(hi) : "r"(u1), "r"(u2));
        dst[(size_t)(w0 + 2*wp  )*64 + h0/2 + hp] = lo;
        dst[(size_t)(w0 + 2*wp+1)*64 + h0/2 + hp] = hi;
    }
}

// score: logits = Q@K^T (K=32), bf16 2-pass. grid (1024,2): y==0 -> H-branch.
// Writes bf16 logits. block 256.
__global__ __launch_bounds__(256) void score_mma()
{
    __shared__ __align__(16) uint32_t Qs[128][36], Ks[128][36];
    const int bs = blockIdx.x, t = threadIdx.x;
    const bool ISH = (blockIdx.y == 0);
    const int wid = t >> 5, lane = t & 31, g8 = lane >> 2, tig = lane & 3;
    const int warp_m = wid & 3, warp_n = wid >> 2;
    const int b = bs >> 7, sfix = bs & 127;
    const size_t base = (size_t)b*HWn*CQn +
        (ISH ? (size_t)sfix*CQn : (size_t)sfix*Wn*CQn);
    const size_t rstride = ISH ? (size_t)Wn*CQn : (size_t)CQn;
    const float* Q = g_q_hw + base;
    const float* K = g_k_hw + base;
    uint32_t* O = (uint32_t*)(ISH ? g_aH : g_aW) + (size_t)bs*128*64;

    #pragma unroll
    for (int i = 0; i < 4; i++) {
        const int idx = i*256 + t, r = idx >> 3, kq = (idx & 7)*4;
        float4 qv = *(const float4*)(Q + (size_t)r*rstride + kq);
        float4 kv = *(const float4*)(K + (size_t)r*rstride + kq);
        uint4 qp = {splitf(qv.x), splitf(qv.y), splitf(qv.z), splitf(qv.w)};
        uint4 kp = {splitf(kv.x), splitf(kv.y), splitf(kv.z), splitf(kv.w)};
        *(uint4*)&Qs[r][kq] = qp;
        *(uint4*)&Ks[r][kq] = kp;
    }
    __syncthreads();

    float acc[2][8][4] = {};
    #pragma unroll
    for (int ks = 0; ks < 2; ks++) {
        const int k0 = ks*16;
        uint32_t ah[2][4], al[2][4];
        #pragma unroll
        for (int mi = 0; mi < 2; mi++) {
            const int m = warp_m*32 + mi*16;
            unzip(*(uint2*)&Qs[m+g8  ][k0 + 2*tig],     ah[mi][0], al[mi][0]);
            unzip(*(uint2*)&Qs[m+g8+8][k0 + 2*tig],     ah[mi][1], al[mi][1]);
            unzip(*(uint2*)&Qs[m+g8  ][k0 + 8 + 2*tig], ah[mi][2], al[mi][2]);
            unzip(*(uint2*)&Qs[m+g8+8][k0 + 8 + 2*tig], ah[mi][3], al[mi][3]);
        }
        #pragma unroll
        for (int ni = 0; ni < 8; ni++) {
            const int n = warp_n*64 + ni*8 + g8;
            uint32_t bh0, bl0, bh1, bl1;
            unzip(*(uint2*)&Ks[n][k0 + 2*tig],     bh0, bl0);
            unzip(*(uint2*)&Ks[n][k0 + 8 + 2*tig], bh1, bl1);
            #pragma unroll
            for (int mi = 0; mi < 2; mi++) {
                mma16(acc[mi][ni], ah[mi][0], ah[mi][1], ah[mi][2], ah[mi][3], bh0, bh1);
                mma16(acc[mi][ni], al[mi][0], al[mi][1], al[mi][2], al[mi][3], bh0, bh1);
            }
        }
    }
    #pragma unroll
    for (int mi = 0; mi < 2; mi++)
        #pragma unroll
        for (int ni = 0; ni < 8; ni++) {
            const int n = warp_n*64 + ni*8 + tig*2;
            #pragma unroll
            for (int hf = 0; hf < 2; hf++) {
                const int m = warp_m*32 + mi*16 + g8 + hf*8;
                float d0 = acc[mi][ni][hf*2], d1 = acc[mi][ni][hf*2+1];
                if (ISH) { if (n == m) d0 = neg_inf_f(); if (n+1 == m) d1 = neg_inf_f(); }
                O[(size_t)m*64 + n/2] = pack2(d0, d1);
            }
        }
}

// softmax: reads bf16 logits, writes bf16 att in place. grid 16384, block 256.
__global__ __launch_bounds__(256) void softmax_kernel()
{
    const int wid = blockIdx.x*8 + (threadIdx.x >> 5), lane = threadIdx.x & 31;
    const int b = wid >> 14, hw = wid & 16383, h = hw >> 7, w = hw & 127;
    const size_t rH = (size_t)(b*Wn + w)*Hh + h;
    const size_t rW = (size_t)(b*Hh + h)*Wn + w;
    uint32_t* aH = (uint32_t*)g_aH + rH*64;
    uint32_t* aW = (uint32_t*)g_aW + rW*64;
    uint2 uh = *(uint2*)(aH + lane*2);
    uint2 uw = *(uint2*)(aW + lane*2);
    float2 h01 = unpack2f(uh.x), h23 = unpack2f(uh.y);
    float2 w01 = unpack2f(uw.x), w23 = unpack2f(uw.y);
    float m = fmaxf(fmaxf(fmaxf(h01.x,h01.y),fmaxf(h23.x,h23.y)),
                    fmaxf(fmaxf(w01.x,w01.y),fmaxf(w23.x,w23.y)));
    #pragma unroll
    for (int off = 16; off; off >>= 1) m = fmaxf(m, __shfl_xor_sync(~0u, m, off));
    h01.x=__expf(h01.x-m); h01.y=__expf(h01.y-m); h23.x=__expf(h23.x-m); h23.y=__expf(h23.y-m);
    w01.x=__expf(w01.x-m); w01.y=__expf(w01.y-m); w23.x=__expf(w23.x-m); w23.y=__expf(w23.y-m);
    float s = h01.x+h01.y+h23.x+h23.y+w01.x+w01.y+w23.x+w23.y;
    #pragma unroll
    for (int off = 16; off; off >>= 1) s += __shfl_xor_sync(~0u, s, off);
    const float inv = 1.f/s;
    *(uint2*)(aH + lane*2) = make_uint2(pack2(h01.x*inv, h01.y*inv), pack2(h23.x*inv, h23.y*inv));
    *(uint2*)(aW + lane*2) = make_uint2(pack2(w01.x*inv, w01.y*inv), pack2(w23.x*inv, w23.y*inv));
}

// out<ISH>: D[128 spatial x 128 c] = att(bf16) @ v^T(bf16), 1-pass k16,
// ldmatrix feed, single-buffer. ISH: writes g_oH[b][h][w][c] (bf16).
// !ISH: adds oH and emits gamma*(D+oH)+x -> out. grid (2,1024), block 256.
template <bool ISH>
__global__ __launch_bounds__(256) void out_mma(const float* __restrict__ x,
                                               const float* __restrict__ gamma,
                                               float* __restrict__ out)
{
    __shared__ __align__(16) uint32_t sm[5120];   // As[128][20]@0, Bs@2560; tb[32][132] reuse
    const int t = threadIdx.x, wid = t >> 5, lane = t & 31;
    const int g8 = lane >> 2, tig = lane & 3;
    const int warp_m = wid & 3, warp_n = wid >> 2;
    const int bs = blockIdx.y, b = bs >> 7, s = bs & 127;
    const int c0 = blockIdx.x * 128;
    const uint32_t* A = (const uint32_t*)(ISH ? g_aH : g_aW) + (size_t)bs*128*64;
    const uint32_t* V = (const uint32_t*)(ISH ? g_vb : g_va) + (size_t)b*Cc*(HWn/2) + s*64;

    const uint32_t sbase = s2u(sm);
    const uint32_t aRow = (uint32_t)(lane & 15);
    const uint32_t aCol = (uint32_t)((lane >> 4) * 16);
    const uint32_t bRow = (uint32_t)((lane & 7) + ((lane >> 4) << 3));
    const uint32_t bCol = (uint32_t)(((lane >> 3) & 1) * 16);

    float acc[2][8][4] = {};
    const int r2 = t >> 1, wq = (t & 1)*8;
    for (int kc = 0; kc < 4; kc++) {
        uint4 a0 = *(const uint4*)(A + (size_t)r2*64 + kc*16 + wq);
        uint4 a1 = *(const uint4*)(A + (size_t)r2*64 + kc*16 + wq + 4);
        uint4 b0 = *(const uint4*)(V + (size_t)(c0 + r2)*(HWn/2) + kc*16 + wq);
        uint4 b1 = *(const uint4*)(V + (size_t)(c0 + r2)*(HWn/2) + kc*16 + wq + 4);
        __syncthreads();
        *(uint4*)&sm[r2*20 + wq]          = a0;
        *(uint4*)&sm[r2*20 + wq + 4]      = a1;
        *(uint4*)&sm[2560 + r2*20 + wq]   = b0;
        *(uint4*)&sm[2560 + r2*20 + wq+4] = b1;
        __syncthreads();
        #pragma unroll
        for (int ks = 0; ks < 2; ks++) {
            const uint32_t ksb = ks*32;
            uint32_t af[2][4], bf[4][4];
            #pragma unroll
            for (int mi = 0; mi < 2; mi++)
                ldm4(af[mi], sbase + (warp_m*32 + mi*16 + aRow)*80 + ksb + aCol);
            #pragma unroll
            for (int pi = 0; pi < 4; pi++)
                ldm4(bf[pi], sbase + 10240 + (warp_n*64 + pi*16 + bRow)*80 + ksb + bCol);
            #pragma unroll
            for (int pi = 0; pi < 4; pi++)
                #pragma unroll
                for (int half = 0; half < 2; half++) {
                    const int ni = pi*2 + half;
                    const uint32_t bb0 = bf[pi][half*2], bb1 = bf[pi][half*2 + 1];
                    #pragma unroll
                    for (int mi = 0; mi < 2; mi++)
                        mma16(acc[mi][ni], af[mi][0], af[mi][1], af[mi][2], af[mi][3], bb0, bb1);
                }
        }
    }

    if (ISH) {
        uint32_t* Ob = (uint32_t*)g_oH;
        #pragma unroll
        for (int mi = 0; mi < 2; mi++)
            #pragma unroll
            for (int ni = 0; ni < 8; ni++) {
                const int m = warp_m*32 + mi*16 + g8;
                const int n = c0 + warp_n*64 + ni*8 + tig*2;
                Ob[((size_t)(b*Hh + m)*Wn + s)*128 + n/2]   = pack2(acc[mi][ni][0], acc[mi][ni][1]);
                Ob[((size_t)(b*Hh + m+8)*Wn + s)*128 + n/2] = pack2(acc[mi][ni][2], acc[mi][ni][3]);
            }
    } else {
        const float gm = gamma[0];
        const uint32_t* o1 = (const uint32_t*)g_oH + (size_t)(b*Hh + s)*Wn*128;
        #pragma unroll
        for (int mi = 0; mi < 2; mi++)
            #pragma unroll
            for (int ni = 0; ni < 8; ni++) {
                const int m = warp_m*32 + mi*16 + g8;
                const int n = c0 + warp_n*64 + ni*8 + tig*2;
                float2 p0 = unpack2f(o1[(size_t)m*128 + n/2]);
                float2 p1 = unpack2f(o1[(size_t)(m+8)*128 + n/2]);
                acc[mi][ni][0] += p0.x; acc[mi][ni][1] += p0.y;
                acc[mi][ni][2] += p1.x; acc[mi][ni][3] += p1.y;
            }
        float* tb = (float*)sm;     // [32][132] floats
        #pragma unroll
        for (int cc = 0; cc < 4; cc++) {
            __syncthreads();
            if (warp_n == (cc >> 1)) {
                const int nib = (cc & 1)*4;
                #pragma unroll
                for (int mi = 0; mi < 2; mi++)
                    #pragma unroll
                    for (int nj = 0; nj < 4; nj++) {
                        const int ni = nib + nj;
                        const int nl = nj*8 + tig*2;
                        const int m = warp_m*32 + mi*16 + g8;
                        tb[nl*132 + m]       = acc[mi][ni][0];
                        tb[(nl+1)*132 + m]   = acc[mi][ni][1];
                        tb[nl*132 + m+8]     = acc[mi][ni][2];
                        tb[(nl+1)*132 + m+8] = acc[mi][ni][3];
                    }
            }
            __syncthreads();
            #pragma unroll
            for (int p = 0; p < 4; p++) {
                const int ci = (t >> 5) + p*8;
                const int w4 = (t & 31)*4;
                const size_t oidx = ((size_t)(b*Cc + c0 + cc*32 + ci)*Hh + s)*Wn + w4;
                float4 xr = *(const float4*)(x + oidx);
                float4 r;
                r.x = gm*tb[ci*132 + w4  ] + xr.x;
                r.y = gm*tb[ci*132 + w4+1] + xr.y;
                r.z = gm*tb[ci*132 + w4+2] + xr.z;
                r.w = gm*tb[ci*132 + w4+3] + xr.w;
                *(float4*)(out + oidx) = r;
            }
        }
    }
}

extern "C" void kernel_launch(void* const* d_in, const int* in_sizes, int n_in,
                              void* d_out, int out_size)
{
    const float* x     = (const float*)d_in[0];
    const float* Wq    = (const float*)d_in[1];
    const float* bq    = (const float*)d_in[2];
    const float* Wk    = (const float*)d_in[3];
    const float* bk    = (const float*)d_in[4];
    const float* Wv    = (const float*)d_in[5];
    const float* bv    = (const float*)d_in[6];
    const float* gamma = (const float*)d_in[7];
    float* out = (float*)d_out;

    prep_kernel<<<320, 256>>>(Wq, bq, Wk, bk, Wv, bv);
    xt_kernel<<<dim3(512, 8, 8), 256>>>(x);
    proj_mma<<<dim3(5, 128, 8), 256>>>();
    vb_kernel<<<dim3(2, 2, Bn*Cc), 256>>>();
    score_mma<<<dim3(1024, 2), 256>>>();
    softmax_kernel<<<16384, 256>>>();
    out_mma<true ><<<dim3(2, 1024), 256>>>(x, gamma, out);
    out_mma<false><<<dim3(2, 1024), 256>>>(x, gamma, out);
}

// round 17
// speedup vs baseline: 1.1605x; 1.0909x over previous
#include <cuda_runtime.h>
#include <cuda_bf16.h>
#include <cstdint>

#define Bn 8
#define Cc 256
#define CQn 32
#define Hh 128
#define Wn 128
#define HWn (Hh*Wn)

__device__ __nv_bfloat16 g_Wh[320*256], g_Wl[320*256];
__device__ float g_bs[320];
__device__ float g_q_hw[(size_t)Bn*HWn*CQn];        // [b][h][w][o]
__device__ float g_k_hw[(size_t)Bn*HWn*CQn];
__device__ __nv_bfloat16 g_va[(size_t)Bn*Cc*HWn];   // [b][c][h][w] bf16
__device__ __nv_bfloat16 g_vb[(size_t)Bn*Cc*HWn];   // [b][c][w][h] bf16
__device__ __nv_bfloat16 g_aH[(size_t)Bn*Wn*Hh*Hh]; // logits -> att (in place, bf16)
__device__ __nv_bfloat16 g_aW[(size_t)Bn*Hh*Wn*Wn];
__device__ __nv_bfloat16 g_oH[(size_t)Bn*HWn*Cc];   // [b][h][w][c] bf16

__device__ __forceinline__ float neg_inf_f() { return __int_as_float(0xff800000); }
__device__ __forceinline__ uint32_t splitf(float f) {
    __nv_bfloat16 h = __float2bfloat16(f);
    __nv_bfloat16 l = __float2bfloat16(f - __bfloat162float(h));
    return (uint32_t)__bfloat16_as_ushort(h) | ((uint32_t)__bfloat16_as_ushort(l) << 16);
}
__device__ __forceinline__ uint32_t pack2(float a, float b) {
    __nv_bfloat162 v = __floats2bfloat162_rn(a, b);
    return *reinterpret_cast<uint32_t*>(&v);
}
__device__ __forceinline__ float2 unpack2f(uint32_t u) {
    __nv_bfloat162 v = *reinterpret_cast<__nv_bfloat162*>(&u);
    return __bfloat1622float2(v);
}
__device__ __forceinline__ void unzip(uint2 p, uint32_t& hi, uint32_t& lo) {
    asm("prmt.b32 %0, %1, %2, 0x5410;" : "=r"(hi) : "r"(p.x), "r"(p.y));
    asm("prmt.b32 %0, %1, %2, 0x7632;" : "=r"(lo) : "r"(p.x), "r"(p.y));
}
__device__ __forceinline__ void mma16(float* d, uint32_t a0, uint32_t a1, uint32_t a2,
                                      uint32_t a3, uint32_t b0, uint32_t b1) {
    asm volatile("mma.sync.aligned.m16n8k16.row.col.f32.bf16.bf16.f32 "
                 "{%0,%1,%2,%3},{%4,%5,%6,%7},{%8,%9},{%0,%1,%2,%3};"
                 : "+f"(d[0]), "+f"(d[1]), "+f"(d[2]), "+f"(d[3])
                 : "r"(a0), "r"(a1), "r"(a2), "r"(a3), "r"(b0), "r"(b1));
}
__device__ __forceinline__ void ldm4(uint32_t* r, uint32_t addr) {
    asm volatile("ldmatrix.sync.aligned.m8n8.x4.shared.b16 {%0,%1,%2,%3}, [%4];"
                 : "=r"(r[0]), "=r"(r[1]), "=r"(r[2]), "=r"(r[3]) : "r"(addr));
}
__device__ __forceinline__ void ldm4t(uint32_t* r, uint32_t addr) {
    asm volatile("ldmatrix.sync.aligned.m8n8.x4.trans.shared.b16 {%0,%1,%2,%3}, [%4];"
                 : "=r"(r[0]), "=r"(r[1]), "=r"(r[2]), "=r"(r[3]) : "r"(addr));
}
__device__ __forceinline__ uint32_t s2u(const void* p) {
    return (uint32_t)__cvta_generic_to_shared(p);
}

// prep: split W rows [Wq;Wk;Wv]. grid 320, block 256.
__global__ __launch_bounds__(256) void prep_kernel(
    const float* __restrict__ Wq, const float* __restrict__ bq,
    const float* __restrict__ Wk, const float* __restrict__ bk,
    const float* __restrict__ Wv, const float* __restrict__ bv)
{
    const int r = blockIdx.x, t = threadIdx.x;
    const float* src; const float* bsrc; int o;
    if (r < 32)      { src = Wq; bsrc = bq; o = r; }
    else if (r < 64) { src = Wk; bsrc = bk; o = r - 32; }
    else             { src = Wv; bsrc = bv; o = r - 64; }
    float v = src[o*256 + t];
    __nv_bfloat16 h = __float2bfloat16(v);
    g_Wh[r*256 + t] = h;
    g_Wl[r*256 + t] = __float2bfloat16(v - __bfloat162float(h));
    if (t == 0) g_bs[r] = bsrc[o];
}

// proj: per (mt,h,b): D[128 px x 64 oc]. Reads x fp32 DIRECTLY (no xt stage):
// splits to bf16 hi/lo in-register, stores [k][px] tiles, feeds A fragments
// via ldmatrix.trans. mt==0 (q,k): 2-pass. mt>=1 (v): 1-pass.
// smem words: XH@0 (32x68), XL@2176, WH@4352 (64x20); tb[64][132] reuse.
// grid (5, 128, 8), block 256.
__global__ __launch_bounds__(256) void proj_mma(const float* __restrict__ x)
{
    __shared__ __align__(16) uint32_t pool[8448];
    __shared__ float s_bias[64];
    const int t = threadIdx.x, wid = t >> 5, lane = t & 31;
    const int g8 = lane >> 2, tig = lane & 3;
    const int warp_m = wid & 3, warp_n = wid >> 2;
    const int mt = blockIdx.x, h = blockIdx.y, b = blockIdx.z;
    const int px0 = h * 128;
    const bool hiPrec = (mt == 0);
    if (t < 64) s_bias[t] = g_bs[mt*64 + t];

    const float* Xg = x + (size_t)b*Cc*HWn + px0;      // row c: + c*HWn
    const __nv_bfloat16* Wh = g_Wh + (size_t)mt*64*Cc;

    const uint32_t pbase = s2u(pool);
    // A (x) via ldmatrix.trans from [k][px], row stride 272 B:
    const uint32_t tRow  = (uint32_t)((lane & 7) + ((lane >> 4) << 3)); // k row
    const uint32_t tByte = (uint32_t)(((lane >> 3) & 1) * 16);          // px half-block
    // B (W) non-trans from [oc][k], row stride 80 B:
    const uint32_t bRow = (uint32_t)((lane & 7) + ((lane >> 4) << 3));
    const uint32_t bCol = (uint32_t)(((lane >> 3) & 1) * 16);

    float acc[2][4][4] = {};
    const int br = t >> 2, bw = (t & 3)*4;      // W loader
    const int xr = t >> 5, xp4 = (t & 31)*4;    // x loader base (r = xr + i*8)

    for (int kc = 0; kc < 8; kc++) {
        float4 xv[4];
        #pragma unroll
        for (int i = 0; i < 4; i++)
            xv[i] = *(const float4*)(Xg + (size_t)(kc*32 + xr + i*8)*HWn + xp4);
        uint4 bhv = *(const uint4*)(Wh + (size_t)br*Cc + kc*32 + bw*2);
        __syncthreads();
        #pragma unroll
        for (int i = 0; i < 4; i++) {
            const int r = xr + i*8, p2 = (t & 31)*2;
            float h0 = __bfloat162float(__float2bfloat16(xv[i].x));
            float h1 = __bfloat162float(__float2bfloat16(xv[i].y));
            float h2 = __bfloat162float(__float2bfloat16(xv[i].z));
            float h3 = __bfloat162float(__float2bfloat16(xv[i].w));
            uint2 hw2 = {pack2(xv[i].x, xv[i].y), pack2(xv[i].z, xv[i].w)};
            *(uint2*)&pool[r*68 + p2] = hw2;
            if (hiPrec) {
                uint2 lw2 = {pack2(xv[i].x - h0, xv[i].y - h1),
                             pack2(xv[i].z - h2, xv[i].w - h3)};
                *(uint2*)&pool[2176 + r*68 + p2] = lw2;
            }
        }
        *(uint4*)&pool[4352 + br*20 + bw] = bhv;
        __syncthreads();
        #pragma unroll
        for (int ks = 0; ks < 2; ks++) {
            uint32_t ahf[2][4], alf[2][4], bf[2][4];
            #pragma unroll
            for (int mi = 0; mi < 2; mi++) {
                const uint32_t addr = (ks*16 + tRow)*272 + (warp_m*32 + mi*16)*2 + tByte;
                ldm4t(ahf[mi], pbase + addr);
                if (hiPrec) ldm4t(alf[mi], pbase + 8704 + addr);
            }
            #pragma unroll
            for (int pi = 0; pi < 2; pi++) {
                const uint32_t rown = (warp_n*32 + pi*16 + bRow)*80 + ks*32 + bCol;
                ldm4(bf[pi], pbase + 17408 + rown);
            }
            #pragma unroll
            for (int pi = 0; pi < 2; pi++)
                #pragma unroll
                for (int half = 0; half < 2; half++) {
                    const int ni = pi*2 + half;
                    const uint32_t b0 = bf[pi][half*2], b1 = bf[pi][half*2 + 1];
                    #pragma unroll
                    for (int mi = 0; mi < 2; mi++) {
                        mma16(acc[mi][ni], ahf[mi][0], ahf[mi][1], ahf[mi][2], ahf[mi][3], b0, b1);
                        if (hiPrec)
                            mma16(acc[mi][ni], alf[mi][0], alf[mi][1], alf[mi][2], alf[mi][3], b0, b1);
                    }
                }
        }
    }

    if (mt == 0) {
        #pragma unroll
        for (int mi = 0; mi < 2; mi++)
            #pragma unroll
            for (int ni = 0; ni < 4; ni++) {
                const int n = warp_n*32 + ni*8 + tig*2;
                const float b0 = s_bias[n], b1 = s_bias[n+1];
                float* hwp = (n < 32 ? g_q_hw : g_k_hw);
                const int o = n & 31;
                #pragma unroll
                for (int hf = 0; hf < 2; hf++) {
                    const int w = warp_m*32 + mi*16 + g8 + hf*8;
                    float2 v = {acc[mi][ni][hf*2] + b0, acc[mi][ni][hf*2+1] + b1};
                    *(float2*)(hwp + ((size_t)(b*Hh + h)*Wn + w)*CQn + o) = v;
                }
            }
    } else {
        float* tb = (float*)pool;   // [64 c][132 px]
        __syncthreads();
        #pragma unroll
        for (int mi = 0; mi < 2; mi++)
            #pragma unroll
            for (int ni = 0; ni < 4; ni++) {
                const int n = warp_n*32 + ni*8 + tig*2;
                const float b0 = s_bias[n], b1 = s_bias[n+1];
                #pragma unroll
                for (int hf = 0; hf < 2; hf++) {
                    const int w = warp_m*32 + mi*16 + g8 + hf*8;
                    tb[n*132 + w]     = acc[mi][ni][hf*2]   + b0;
                    tb[(n+1)*132 + w] = acc[mi][ni][hf*2+1] + b1;
                }
            }
        __syncthreads();
        const int c = t >> 2, p4 = (t & 3)*32;
        uint32_t* dst = (uint32_t*)(g_va + ((size_t)(b*Cc + (mt-1)*64 + c))*HWn + px0 + p4);
        #pragma unroll
        for (int i = 0; i < 32; i += 8) {
            uint4 u;
            u.x = pack2(tb[c*132+p4+i  ], tb[c*132+p4+i+1]);
            u.y = pack2(tb[c*132+p4+i+2], tb[c*132+p4+i+3]);
            u.z = pack2(tb[c*132+p4+i+4], tb[c*132+p4+i+5]);
            u.w = pack2(tb[c*132+p4+i+6], tb[c*132+p4+i+7]);
            *(uint4*)(dst + i/2) = u;
        }
    }
}

// vb: bf16 transpose g_va[c][h][w] -> g_vb[c][w][h]. grid (2,2,Bn*Cc), block 256.
__global__ __launch_bounds__(256) void vb_kernel()
{
    __shared__ uint32_t sm[64][33];
    const int bc = blockIdx.z, w0 = blockIdx.x*64, h0 = blockIdx.y*64;
    const int t = threadIdx.x;
    const uint32_t* src = (const uint32_t*)g_va + (size_t)bc*(HWn/2);
    uint32_t* dst = (uint32_t*)g_vb + (size_t)bc*(HWn/2);
    #pragma unroll
    for (int i = 0; i < 8; i++) {
        const int idx = i*256 + t, r = idx >> 5, wd = idx & 31;
        sm[r][wd] = src[(size_t)(h0 + r)*64 + w0/2 + wd];
    }
    __syncthreads();
    #pragma unroll
    for (int i = 0; i < 4; i++) {
        const int idx = i*256 + t, wp = idx >> 5, hp = idx & 31;
        uint32_t u1 = sm[2*hp][wp], u2 = sm[2*hp+1][wp];
        uint32_t lo, hi;
        asm("prmt.b32 %0, %1, %2, 0x5410;" : "=r"(lo) : "r"(u1), "r"(u2));
        asm("prmt.b32 %0, %1, %2, 0x7632;" : "=r"(hi) : "r"(u1), "r"(u2));
        dst[(size_t)(w0 + 2*wp  )*64 + h0/2 + hp] = lo;
        dst[(size_t)(w0 + 2*wp+1)*64 + h0/2 + hp] = hi;
    }
}

// score: logits = Q@K^T (K=32), bf16 2-pass. grid (1024,2): y==0 -> H-branch.
__global__ __launch_bounds__(256) void score_mma()
{
    __shared__ __align__(16) uint32_t Qs[128][36], Ks[128][36];
    const int bs = blockIdx.x, t = threadIdx.x;
    const bool ISH = (blockIdx.y == 0);
    const int wid = t >> 5, lane = t & 31, g8 = lane >> 2, tig = lane & 3;
    const int warp_m = wid & 3, warp_n = wid >> 2;
    const int b = bs >> 7, sfix = bs & 127;
    const size_t base = (size_t)b*HWn*CQn +
        (ISH ? (size_t)sfix*CQn : (size_t)sfix*Wn*CQn);
    const size_t rstride = ISH ? (size_t)Wn*CQn : (size_t)CQn;
    const float* Q = g_q_hw + base;
    const float* K = g_k_hw + base;
    uint32_t* O = (uint32_t*)(ISH ? g_aH : g_aW) + (size_t)bs*128*64;

    #pragma unroll
    for (int i = 0; i < 4; i++) {
        const int idx = i*256 + t, r = idx >> 3, kq = (idx & 7)*4;
        float4 qv = *(const float4*)(Q + (size_t)r*rstride + kq);
        float4 kv = *(const float4*)(K + (size_t)r*rstride + kq);
        uint4 qp = {splitf(qv.x), splitf(qv.y), splitf(qv.z), splitf(qv.w)};
        uint4 kp = {splitf(kv.x), splitf(kv.y), splitf(kv.z), splitf(kv.w)};
        *(uint4*)&Qs[r][kq] = qp;
        *(uint4*)&Ks[r][kq] = kp;
    }
    __syncthreads();

    float acc[2][8][4] = {};
    #pragma unroll
    for (int ks = 0; ks < 2; ks++) {
        const int k0 = ks*16;
        uint32_t ah[2][4], al[2][4];
        #pragma unroll
        for (int mi = 0; mi < 2; mi++) {
            const int m = warp_m*32 + mi*16;
            unzip(*(uint2*)&Qs[m+g8  ][k0 + 2*tig],     ah[mi][0], al[mi][0]);
            unzip(*(uint2*)&Qs[m+g8+8][k0 + 2*tig],     ah[mi][1], al[mi][1]);
            unzip(*(uint2*)&Qs[m+g8  ][k0 + 8 + 2*tig], ah[mi][2], al[mi][2]);
            unzip(*(uint2*)&Qs[m+g8+8][k0 + 8 + 2*tig], ah[mi][3], al[mi][3]);
        }
        #pragma unroll
        for (int ni = 0; ni < 8; ni++) {
            const int n = warp_n*64 + ni*8 + g8;
            uint32_t bh0, bl0, bh1, bl1;
            unzip(*(uint2*)&Ks[n][k0 + 2*tig],     bh0, bl0);
            unzip(*(uint2*)&Ks[n][k0 + 8 + 2*tig], bh1, bl1);
            #pragma unroll
            for (int mi = 0; mi < 2; mi++) {
                mma16(acc[mi][ni], ah[mi][0], ah[mi][1], ah[mi][2], ah[mi][3], bh0, bh1);
                mma16(acc[mi][ni], al[mi][0], al[mi][1], al[mi][2], al[mi][3], bh0, bh1);
            }
        }
    }
    #pragma unroll
    for (int mi = 0; mi < 2; mi++)
        #pragma unroll
        for (int ni = 0; ni < 8; ni++) {
            const int n = warp_n*64 + ni*8 + tig*2;
            #pragma unroll
            for (int hf = 0; hf < 2; hf++) {
                const int m = warp_m*32 + mi*16 + g8 + hf*8;
                float d0 = acc[mi][ni][hf*2], d1 = acc[mi][ni][hf*2+1];
                if (ISH) { if (n == m) d0 = neg_inf_f(); if (n+1 == m) d1 = neg_inf_f(); }
                O[(size_t)m*64 + n/2] = pack2(d0, d1);
            }
        }
}

// softmax: reads bf16 logits, writes bf16 att in place. grid 16384, block 256.
__global__ __launch_bounds__(256) void softmax_kernel()
{
    const int wid = blockIdx.x*8 + (threadIdx.x >> 5), lane = threadIdx.x & 31;
    const int b = wid >> 14, hw = wid & 16383, h = hw >> 7, w = hw & 127;
    const size_t rH = (size_t)(b*Wn + w)*Hh + h;
    const size_t rW = (size_t)(b*Hh + h)*Wn + w;
    uint32_t* aH = (uint32_t*)g_aH + rH*64;
    uint32_t* aW = (uint32_t*)g_aW + rW*64;
    uint2 uh = *(uint2*)(aH + lane*2);
    uint2 uw = *(uint2*)(aW + lane*2);
    float2 h01 = unpack2f(uh.x), h23 = unpack2f(uh.y);
    float2 w01 = unpack2f(uw.x), w23 = unpack2f(uw.y);
    float m = fmaxf(fmaxf(fmaxf(h01.x,h01.y),fmaxf(h23.x,h23.y)),
                    fmaxf(fmaxf(w01.x,w01.y),fmaxf(w23.x,w23.y)));
    #pragma unroll
    for (int off = 16; off; off >>= 1) m = fmaxf(m, __shfl_xor_sync(~0u, m, off));
    h01.x=__expf(h01.x-m); h01.y=__expf(h01.y-m); h23.x=__expf(h23.x-m); h23.y=__expf(h23.y-m);
    w01.x=__expf(w01.x-m); w01.y=__expf(w01.y-m); w23.x=__expf(w23.x-m); w23.y=__expf(w23.y-m);
    float s = h01.x+h01.y+h23.x+h23.y+w01.x+w01.y+w23.x+w23.y;
    #pragma unroll
    for (int off = 16; off; off >>= 1) s += __shfl_xor_sync(~0u, s, off);
    const float inv = 1.f/s;
    *(uint2*)(aH + lane*2) = make_uint2(pack2(h01.x*inv, h01.y*inv), pack2(h23.x*inv, h23.y*inv));
    *(uint2*)(aW + lane*2) = make_uint2(pack2(w01.x*inv, w01.y*inv), pack2(w23.x*inv, w23.y*inv));
}

// out<ISH>: D[128 spatial x 128 c] = att(bf16) @ v^T(bf16), 1-pass k16,
// ldmatrix feed, single-buffer. ISH: writes g_oH[b][h][w][c] (bf16).
// !ISH: adds oH and emits gamma*(D+oH)+x -> out. grid (2,1024), block 256.
template <bool ISH>
__global__ __launch_bounds__(256) void out_mma(const float* __restrict__ x,
                                               const float* __restrict__ gamma,
                                               float* __restrict__ out)
{
    __shared__ __align__(16) uint32_t sm[5120];   // As[128][20]@0, Bs@2560; tb[32][132] reuse
    const int t = threadIdx.x, wid = t >> 5, lane = t & 31;
    const int g8 = lane >> 2, tig = lane & 3;
    const int warp_m = wid & 3, warp_n = wid >> 2;
    const int bs = blockIdx.y, b = bs >> 7, s = bs & 127;
    const int c0 = blockIdx.x * 128;
    const uint32_t* A = (const uint32_t*)(ISH ? g_aH : g_aW) + (size_t)bs*128*64;
    const uint32_t* V = (const uint32_t*)(ISH ? g_vb : g_va) + (size_t)b*Cc*(HWn/2) + s*64;

    const uint32_t sbase = s2u(sm);
    const uint32_t aRow = (uint32_t)(lane & 15);
    const uint32_t aCol = (uint32_t)((lane >> 4) * 16);
    const uint32_t bRow = (uint32_t)((lane & 7) + ((lane >> 4) << 3));
    const uint32_t bCol = (uint32_t)(((lane >> 3) & 1) * 16);

    float acc[2][8][4] = {};
    const int r2 = t >> 1, wq = (t & 1)*8;
    for (int kc = 0; kc < 4; kc++) {
        uint4 a0 = *(const uint4*)(A + (size_t)r2*64 + kc*16 + wq);
        uint4 a1 = *(const uint4*)(A + (size_t)r2*64 + kc*16 + wq + 4);
        uint4 b0 = *(const uint4*)(V + (size_t)(c0 + r2)*(HWn/2) + kc*16 + wq);
        uint4 b1 = *(const uint4*)(V + (size_t)(c0 + r2)*(HWn/2) + kc*16 + wq + 4);
        __syncthreads();
        *(uint4*)&sm[r2*20 + wq]          = a0;
        *(uint4*)&sm[r2*20 + wq + 4]      = a1;
        *(uint4*)&sm[2560 + r2*20 + wq]   = b0;
        *(uint4*)&sm[2560 + r2*20 + wq+4] = b1;
        __syncthreads();
        #pragma unroll
        for (int ks = 0; ks < 2; ks++) {
            const uint32_t ksb = ks*32;
            uint32_t af[2][4], bf[4][4];
            #pragma unroll
            for (int mi = 0; mi < 2; mi++)
                ldm4(af[mi], sbase + (warp_m*32 + mi*16 + aRow)*80 + ksb + aCol);
            #pragma unroll
            for (int pi = 0; pi < 4; pi++)
                ldm4(bf[pi], sbase + 10240 + (warp_n*64 + pi*16 + bRow)*80 + ksb + bCol);
            #pragma unroll
            for (int pi = 0; pi < 4; pi++)
                #pragma unroll
                for (int half = 0; half < 2; half++) {
                    const int ni = pi*2 + half;
                    const uint32_t bb0 = bf[pi][half*2], bb1 = bf[pi][half*2 + 1];
                    #pragma unroll
                    for (int mi = 0; mi < 2; mi++)
                        mma16(acc[mi][ni], af[mi][0], af[mi][1], af[mi][2], af[mi][3], bb0, bb1);
                }
        }
    }

    if (ISH) {
        uint32_t* Ob = (uint32_t*)g_oH;
        #pragma unroll
        for (int mi = 0; mi < 2; mi++)
            #pragma unroll
            for (int ni = 0; ni < 8; ni++) {
                const int m = warp_m*32 + mi*16 + g8;
                const int n = c0 + warp_n*64 + ni*8 + tig*2;
                Ob[((size_t)(b*Hh + m)*Wn + s)*128 + n/2]   = pack2(acc[mi][ni][0], acc[mi][ni][1]);
                Ob[((size_t)(b*Hh + m+8)*Wn + s)*128 + n/2] = pack2(acc[mi][ni][2], acc[mi][ni][3]);
            }
    } else {
        const float gm = gamma[0];
        const uint32_t* o1 = (const uint32_t*)g_oH + (size_t)(b*Hh + s)*Wn*128;
        #pragma unroll
        for (int mi = 0; mi < 2; mi++)
            #pragma unroll
            for (int ni = 0; ni < 8; ni++) {
                const int m = warp_m*32 + mi*16 + g8;
                const int n = c0 + warp_n*64 + ni*8 + tig*2;
                float2 p0 = unpack2f(o1[(size_t)m*128 + n/2]);
                float2 p1 = unpack2f(o1[(size_t)(m+8)*128 + n/2]);
                acc[mi][ni][0] += p0.x; acc[mi][ni][1] += p0.y;
                acc[mi][ni][2] += p1.x; acc[mi][ni][3] += p1.y;
            }
        float* tb = (float*)sm;     // [32][132] floats
        #pragma unroll
        for (int cc = 0; cc < 4; cc++) {
            __syncthreads();
            if (warp_n == (cc >> 1)) {
                const int nib = (cc & 1)*4;
                #pragma unroll
                for (int mi = 0; mi < 2; mi++)
                    #pragma unroll
                    for (int nj = 0; nj < 4; nj++) {
                        const int ni = nib + nj;
                        const int nl = nj*8 + tig*2;
                        const int m = warp_m*32 + mi*16 + g8;
                        tb[nl*132 + m]       = acc[mi][ni][0];
                        tb[(nl+1)*132 + m]   = acc[mi][ni][1];
                        tb[nl*132 + m+8]     = acc[mi][ni][2];
                        tb[(nl+1)*132 + m+8] = acc[mi][ni][3];
                    }
            }
            __syncthreads();
            #pragma unroll
            for (int p = 0; p < 4; p++) {
                const int ci = (t >> 5) + p*8;
                const int w4 = (t & 31)*4;
                const size_t oidx = ((size_t)(b*Cc + c0 + cc*32 + ci)*Hh + s)*Wn + w4;
                float4 xr = *(const float4*)(x + oidx);
                float4 r;
                r.x = gm*tb[ci*132 + w4  ] + xr.x;
                r.y = gm*tb[ci*132 + w4+1] + xr.y;
                r.z = gm*tb[ci*132 + w4+2] + xr.z;
                r.w = gm*tb[ci*132 + w4+3] + xr.w;
                *(float4*)(out + oidx) = r;
            }
        }
    }
}

extern "C" void kernel_launch(void* const* d_in, const int* in_sizes, int n_in,
                              void* d_out, int out_size)
{
    const float* x     = (const float*)d_in[0];
    const float* Wq    = (const float*)d_in[1];
    const float* bq    = (const float*)d_in[2];
    const float* Wk    = (const float*)d_in[3];
    const float* bk    = (const float*)d_in[4];
    const float* Wv    = (const float*)d_in[5];
    const float* bv    = (const float*)d_in[6];
    const float* gamma = (const float*)d_in[7];
    float* out = (float*)d_out;

    prep_kernel<<<320, 256>>>(Wq, bq, Wk, bk, Wv, bv);
    proj_mma<<<dim3(5, 128, 8), 256>>>(x);
    vb_kernel<<<dim3(2, 2, Bn*Cc), 256>>>();
    score_mma<<<dim3(1024, 2), 256>>>();
    softmax_kernel<<<16384, 256>>>();
    out_mma<true ><<<dim3(2, 1024), 256>>>(x, gamma, out);
    out_mma<false><<<dim3(2, 1024), 256>>>(x, gamma, out);
}